// round 6
// baseline (speedup 1.0000x reference)
#include <cuda_runtime.h>
#include <cuda_bf16.h>
#include <math.h>
#include <stdint.h>

#define B_SZ   4
#define T_SEQ  1024
#define DIMC   768
#define NH     12
#define DH     64
#define NROWS  (B_SZ * T_SEQ)          // 4096
#define QKV_N  (3 * DIMC)              // 2304
#define KDIM   768

// ============================================================================
// Scratch (static device globals; no allocation)
// ============================================================================
__device__ float g_qkv_c [(size_t)NROWS * QKV_N];
__device__ float g_qkv_ac[(size_t)NROWS * QKV_N];
__device__ float g_attn_c [(size_t)NROWS * DIMC];
__device__ float g_attn_ac[(size_t)NROWS * DIMC];
__device__ float g_proj_c [(size_t)NROWS * DIMC];
__device__ float g_proj_ac[(size_t)NROWS * DIMC];

// ============================================================================
// helpers
// ============================================================================
__device__ __forceinline__ uint32_t smem_u32(const void* p) {
    uint32_t a;
    asm("{ .reg .u64 t; cvta.to.shared.u64 t, %1; cvt.u32.u64 %0, t; }" : "=r"(a) : "l"(p));
    return a;
}

__device__ __forceinline__ void cp16(uint32_t dst, const void* src) {
    asm volatile("cp.async.cg.shared.global [%0], [%1], 16;" :: "r"(dst), "l"(src));
}
#define CP_COMMIT() asm volatile("cp.async.commit_group;")

__device__ __forceinline__ uint32_t f32_to_tf32(float f) {
    uint32_t r;
    asm("cvt.rna.tf32.f32 %0, %1;" : "=r"(r) : "f"(f));
    return r;
}

__device__ __forceinline__ void mma_tf32(float& d0, float& d1, float& d2, float& d3,
                                         uint32_t a0, uint32_t a1, uint32_t a2, uint32_t a3,
                                         uint32_t b0, uint32_t b1) {
    asm volatile(
        "mma.sync.aligned.m16n8k8.row.col.f32.tf32.tf32.f32 "
        "{%0,%1,%2,%3}, {%4,%5,%6,%7}, {%8,%9}, {%0,%1,%2,%3};"
        : "+f"(d0), "+f"(d1), "+f"(d2), "+f"(d3)
        : "r"(a0), "r"(a1), "r"(a2), "r"(a3), "r"(b0), "r"(b1));
}

// ============================================================================
// tf32 GEMM, cp.async 3-stage pipeline, batched over z (2 weight sets).
// Templated over BN_T (128 for QKV, 64 for proj — better wave quantization).
// Block tile 128xBN_T, BK=16, 256 threads (8 warps, 4x2; warp tile 32x(BN_T/2)).
// ============================================================================
#define BM 128
#define BK 16
#define GSTG 3
#define ASTR 20
#define A_STAGE (BM * ASTR)            // 2560 floats

template<int BN_T>
__global__ void __launch_bounds__(256, 2) gemm_tf32_pipe(
    const float* __restrict__ A0, const float* __restrict__ A1,
    const float* __restrict__ W0, const float* __restrict__ W1,
    const float* __restrict__ bias0, const float* __restrict__ bias1,
    float* __restrict__ C0, float* __restrict__ C1,
    int M, int N, int K)
{
    constexpr int BSTR = BN_T + 4;
    constexpr int B_STAGE = BK * BSTR;
    constexpr int NT = BN_T / 16;            // n-tiles per warp
    constexpr int CHB = BN_T / 64;           // B 16B-chunks per thread
    constexpr int CH_PER_ROW = BN_T / 4;

    extern __shared__ float smf[];
    float* Asm = smf;
    float* Bsm = smf + GSTG * A_STAGE;
    const uint32_t sA = smem_u32(Asm);
    const uint32_t sB = smem_u32(Bsm);

    const int z = blockIdx.z;
    const float* A    = z ? A1 : A0;
    const float* W    = z ? W1 : W0;
    const float* bias = z ? bias1 : bias0;
    float*       C    = z ? C1 : C0;

    const int tid  = threadIdx.x;
    const int lane = tid & 31;
    const int warp = tid >> 5;
    const int wm   = warp & 3;
    const int wn   = warp >> 2;
    const int lrow = lane >> 2;
    const int lcol = lane & 3;

    const int m0 = blockIdx.y * BM;
    const int n0 = blockIdx.x * BN_T;

    const int nk = K / BK;

    auto load_stage = [&](int s, int kb) {
        const int k0 = kb * BK;
        const uint32_t aB = sA + (uint32_t)(s * A_STAGE) * 4;
        const uint32_t bB = sB + (uint32_t)(s * B_STAGE) * 4;
#pragma unroll
        for (int i = 0; i < 2; i++) {
            int c = tid + i * 256;
            int r = c >> 2, kc = (c & 3) * 4;
            cp16(aB + (uint32_t)(r * ASTR + kc) * 4,
                 &A[(size_t)(m0 + r) * K + k0 + kc]);
        }
#pragma unroll
        for (int i = 0; i < CHB; i++) {
            int c = tid + i * 256;
            int kr = c / CH_PER_ROW, nc = (c % CH_PER_ROW) * 4;
            cp16(bB + (uint32_t)(kr * BSTR + nc) * 4,
                 &W[(size_t)(k0 + kr) * N + n0 + nc]);
        }
        CP_COMMIT();
    };

    float acc[2][NT][4];
#pragma unroll
    for (int i = 0; i < 2; i++)
#pragma unroll
        for (int j = 0; j < NT; j++)
#pragma unroll
            for (int v = 0; v < 4; v++) acc[i][j][v] = 0.0f;

    load_stage(0, 0);
    load_stage(1, 1);

    for (int kb = 0; kb < nk; kb++) {
        const int s = kb % GSTG;
        if (kb + 1 < nk) asm volatile("cp.async.wait_group 1;");
        else             asm volatile("cp.async.wait_group 0;");
        __syncthreads();

        if (kb + 2 < nk) load_stage((kb + 2) % GSTG, kb + 2);

        const float* As = Asm + s * A_STAGE;
        const float* Bs = Bsm + s * B_STAGE;

#pragma unroll
        for (int ks = 0; ks < 2; ks++) {
            const int kk = ks * 8;
            uint32_t af[2][4];
#pragma unroll
            for (int mt = 0; mt < 2; mt++) {
                int r = wm * 32 + mt * 16 + lrow;
                af[mt][0] = __float_as_uint(As[r * ASTR + kk + lcol]);
                af[mt][1] = __float_as_uint(As[(r + 8) * ASTR + kk + lcol]);
                af[mt][2] = __float_as_uint(As[r * ASTR + kk + lcol + 4]);
                af[mt][3] = __float_as_uint(As[(r + 8) * ASTR + kk + lcol + 4]);
            }
#pragma unroll
            for (int nt = 0; nt < NT; nt++) {
                int n = wn * (BN_T / 2) + nt * 8 + lrow;
                uint32_t b0 = __float_as_uint(Bs[(kk + lcol) * BSTR + n]);
                uint32_t b1 = __float_as_uint(Bs[(kk + lcol + 4) * BSTR + n]);
#pragma unroll
                for (int mt = 0; mt < 2; mt++) {
                    mma_tf32(acc[mt][nt][0], acc[mt][nt][1], acc[mt][nt][2], acc[mt][nt][3],
                             af[mt][0], af[mt][1], af[mt][2], af[mt][3], b0, b1);
                }
            }
        }
        // no trailing syncthreads: with GSTG=3 the next iteration's top sync
        // orders compute(kb) before any cp.async into stage (kb)%3 at kb+1+...
    }

    // epilogue
#pragma unroll
    for (int mt = 0; mt < 2; mt++) {
        int r = m0 + wm * 32 + mt * 16 + lrow;
#pragma unroll
        for (int nt = 0; nt < NT; nt++) {
            int c = n0 + wn * (BN_T / 2) + nt * 8 + lcol * 2;
            float2 bv = *(const float2*)&bias[c];
            float2 o0, o1;
            o0.x = acc[mt][nt][0] + bv.x;
            o0.y = acc[mt][nt][1] + bv.y;
            o1.x = acc[mt][nt][2] + bv.x;
            o1.y = acc[mt][nt][3] + bv.y;
            *(float2*)&C[(size_t)r * N + c]       = o0;
            *(float2*)&C[(size_t)(r + 8) * N + c] = o1;
        }
    }
}

// ============================================================================
// Tensor-core flash attention (tf32 mma.sync), cp.async double-buffered K/V.
// BM=64 query rows per block, BN=64 keys per tile, 128 threads (4 warps).
// K/V stored as raw f32 bits (HMMA truncates to tf32).
// ============================================================================
#define AT_BM 64
#define AT_BN 64
#define KSTR 68
#define VSTR 72
#define PSTR 68
#define KV_STAGE (64 * KSTR + 64 * VSTR)          // 8960 u32 per stage
#define AT_SMEM ((2 * KV_STAGE + 64 * PSTR) * 4)  // 89088 B

__global__ void __launch_bounds__(128) attn_mma(
    const float* __restrict__ qkv_c, const float* __restrict__ qkv_ac,
    float* __restrict__ out_c, float* __restrict__ out_ac)
{
    extern __shared__ uint32_t asmem[];
    uint32_t* Ps = asmem + 2 * KV_STAGE;
    const uint32_t sbase = smem_u32(asmem);

    const int causal = (blockIdx.z < 4);
    const int b  = blockIdx.z & 3;
    const int h  = blockIdx.y;
    const int m0 = blockIdx.x * AT_BM;
    const float* qkv = causal ? qkv_c : qkv_ac;
    float* outp      = causal ? out_c : out_ac;

    const int tid  = threadIdx.x;
    const int warp = tid >> 5;
    const int lane = tid & 31;
    const int lrow = lane >> 2;
    const int lcol = lane & 3;

    const float* qbase = qkv + (size_t)b * T_SEQ * QKV_N + h * DH;
    const float* kbase = qbase + DIMC;
    const float* vbase = qbase + 2 * DIMC;

    const int n_start = causal ? 0 : m0;
    const int n_end   = causal ? (m0 + AT_BM) : T_SEQ;

    auto issue_kv = [&](int s, int n0) {
        const uint32_t kB = sbase + (uint32_t)(s * KV_STAGE) * 4;
        const uint32_t vB = kB + (uint32_t)(64 * KSTR) * 4;
#pragma unroll
        for (int i = 0; i < 8; i++) {
            int idx = i * 128 + tid;
            int r = idx >> 4, c4 = (idx & 15) * 4;
            cp16(kB + (uint32_t)(r * KSTR + c4) * 4,
                 &kbase[(size_t)(n0 + r) * QKV_N + c4]);
            cp16(vB + (uint32_t)(r * VSTR + c4) * 4,
                 &vbase[(size_t)(n0 + r) * QKV_N + c4]);
        }
        CP_COMMIT();
    };

    // prefetch first K/V tile, then stage Q
    issue_kv(0, n_start);

#pragma unroll
    for (int i = 0; i < 8; i++) {
        int idx = i * 128 + tid;
        int r = idx >> 4, c4 = (idx & 15) * 4;
        float4 q = *(const float4*)&qbase[(size_t)(m0 + r) * QKV_N + c4];
        float* p = (float*)&Ps[r * PSTR + c4];
        p[0] = q.x; p[1] = q.y; p[2] = q.z; p[3] = q.w;
    }
    __syncthreads();

    uint32_t qa[8][4];
    {
        const float* Pf = (const float*)Ps;
        const int r0 = (warp * 16 + lrow) * PSTR;
        const int r1 = r0 + 8 * PSTR;
#pragma unroll
        for (int kt = 0; kt < 8; kt++) {
            int c = kt * 8 + lcol;
            qa[kt][0] = f32_to_tf32(Pf[r0 + c]     * 0.125f);
            qa[kt][1] = f32_to_tf32(Pf[r1 + c]     * 0.125f);
            qa[kt][2] = f32_to_tf32(Pf[r0 + c + 4] * 0.125f);
            qa[kt][3] = f32_to_tf32(Pf[r1 + c + 4] * 0.125f);
        }
    }
    // qa reads only this warp's rows of Ps; loop P-stores are warp-local too.

    float o[8][4];
#pragma unroll
    for (int i = 0; i < 8; i++)
#pragma unroll
        for (int j = 0; j < 4; j++) o[i][j] = 0.0f;
    float mr0 = -INFINITY, mr1 = -INFINITY, l0 = 0.0f, l1 = 0.0f;

    const int r0g = m0 + warp * 16 + lrow;
    const int r1g = r0g + 8;

    int buf = 0;
    for (int n0 = n_start; n0 < n_end; n0 += AT_BN) {
        asm volatile("cp.async.wait_group 0;");
        __syncthreads();                        // KV[buf] ready; prev compute done
        if (n0 + AT_BN < n_end) issue_kv(buf ^ 1, n0 + AT_BN);

        const uint32_t* Ks = asmem + buf * KV_STAGE;
        const uint32_t* Vs = Ks + 64 * KSTR;

        // ---- S = Q K^T ----
        float s[8][4];
#pragma unroll
        for (int nt = 0; nt < 8; nt++) {
            s[nt][0] = s[nt][1] = s[nt][2] = s[nt][3] = 0.0f;
            const int kr = (nt * 8 + lrow) * KSTR;
#pragma unroll
            for (int kt = 0; kt < 8; kt++) {
                uint32_t b0 = Ks[kr + kt * 8 + lcol];
                uint32_t b1 = Ks[kr + kt * 8 + lcol + 4];
                mma_tf32(s[nt][0], s[nt][1], s[nt][2], s[nt][3],
                         qa[kt][0], qa[kt][1], qa[kt][2], qa[kt][3], b0, b1);
            }
        }

        const bool need_mask = causal ? (n0 + AT_BN - 1 > m0 + warp * 16)
                                      : (n0 < m0 + warp * 16 + 15);
        if (need_mask) {
#pragma unroll
            for (int nt = 0; nt < 8; nt++) {
                int c0 = n0 + nt * 8 + 2 * lcol;
                int c1 = c0 + 1;
                if (causal) {
                    if (c0 > r0g) s[nt][0] = -INFINITY;
                    if (c1 > r0g) s[nt][1] = -INFINITY;
                    if (c0 > r1g) s[nt][2] = -INFINITY;
                    if (c1 > r1g) s[nt][3] = -INFINITY;
                } else {
                    if (c0 < r0g) s[nt][0] = -INFINITY;
                    if (c1 < r0g) s[nt][1] = -INFINITY;
                    if (c0 < r1g) s[nt][2] = -INFINITY;
                    if (c1 < r1g) s[nt][3] = -INFINITY;
                }
            }
        }

        // ---- online softmax (quad shuffles) ----
        float t0 = -INFINITY, t1 = -INFINITY;
#pragma unroll
        for (int nt = 0; nt < 8; nt++) {
            t0 = fmaxf(t0, fmaxf(s[nt][0], s[nt][1]));
            t1 = fmaxf(t1, fmaxf(s[nt][2], s[nt][3]));
        }
        t0 = fmaxf(t0, __shfl_xor_sync(0xffffffff, t0, 1));
        t0 = fmaxf(t0, __shfl_xor_sync(0xffffffff, t0, 2));
        t1 = fmaxf(t1, __shfl_xor_sync(0xffffffff, t1, 1));
        t1 = fmaxf(t1, __shfl_xor_sync(0xffffffff, t1, 2));
        float nm0 = fmaxf(mr0, t0), nm1 = fmaxf(mr1, t1);
        float sc0 = __expf(mr0 - nm0), sc1 = __expf(mr1 - nm1);

        float sum0 = 0.0f, sum1 = 0.0f;
#pragma unroll
        for (int nt = 0; nt < 8; nt++) {
            s[nt][0] = __expf(s[nt][0] - nm0); sum0 += s[nt][0];
            s[nt][1] = __expf(s[nt][1] - nm0); sum0 += s[nt][1];
            s[nt][2] = __expf(s[nt][2] - nm1); sum1 += s[nt][2];
            s[nt][3] = __expf(s[nt][3] - nm1); sum1 += s[nt][3];
        }
        sum0 += __shfl_xor_sync(0xffffffff, sum0, 1);
        sum0 += __shfl_xor_sync(0xffffffff, sum0, 2);
        sum1 += __shfl_xor_sync(0xffffffff, sum1, 1);
        sum1 += __shfl_xor_sync(0xffffffff, sum1, 2);
        l0 = l0 * sc0 + sum0;
        l1 = l1 * sc1 + sum1;
        mr0 = nm0; mr1 = nm1;

#pragma unroll
        for (int nt = 0; nt < 8; nt++) {
            o[nt][0] *= sc0; o[nt][1] *= sc0;
            o[nt][2] *= sc1; o[nt][3] *= sc1;
        }

        // ---- P -> smem (warp-private region) ----
        {
            const int pr0 = (warp * 16 + lrow) * PSTR;
            const int pr1 = pr0 + 8 * PSTR;
#pragma unroll
            for (int nt = 0; nt < 8; nt++) {
                int c = nt * 8 + 2 * lcol;
                Ps[pr0 + c]     = f32_to_tf32(s[nt][0]);
                Ps[pr0 + c + 1] = f32_to_tf32(s[nt][1]);
                Ps[pr1 + c]     = f32_to_tf32(s[nt][2]);
                Ps[pr1 + c + 1] = f32_to_tf32(s[nt][3]);
            }
        }
        __syncwarp();

        // ---- O += P @ V ----
        {
            const int pr0 = (warp * 16 + lrow) * PSTR;
            const int pr1 = pr0 + 8 * PSTR;
#pragma unroll
            for (int kt = 0; kt < 8; kt++) {
                uint32_t a0 = Ps[pr0 + kt * 8 + lcol];
                uint32_t a1 = Ps[pr1 + kt * 8 + lcol];
                uint32_t a2 = Ps[pr0 + kt * 8 + lcol + 4];
                uint32_t a3 = Ps[pr1 + kt * 8 + lcol + 4];
                const int vr0 = (kt * 8 + lcol) * VSTR;
                const int vr1 = (kt * 8 + lcol + 4) * VSTR;
#pragma unroll
                for (int nt = 0; nt < 8; nt++) {
                    uint32_t b0 = Vs[vr0 + nt * 8 + lrow];
                    uint32_t b1 = Vs[vr1 + nt * 8 + lrow];
                    mma_tf32(o[nt][0], o[nt][1], o[nt][2], o[nt][3],
                             a0, a1, a2, a3, b0, b1);
                }
            }
        }
        buf ^= 1;
    }

    float inv0 = 1.0f / l0, inv1 = 1.0f / l1;
    size_t ob = (size_t)(b * T_SEQ + r0g) * DIMC + h * DH;
#pragma unroll
    for (int nt = 0; nt < 8; nt++) {
        int c = nt * 8 + 2 * lcol;
        float2 w0, w1;
        w0.x = o[nt][0] * inv0; w0.y = o[nt][1] * inv0;
        w1.x = o[nt][2] * inv1; w1.y = o[nt][3] * inv1;
        *(float2*)&outp[ob + c]            = w0;
        *(float2*)&outp[ob + 8 * DIMC + c] = w1;
    }
}

// ============================================================================
// Fused residual + LayerNorm (unchanged)
// ============================================================================
__global__ void residual_ln(const float* __restrict__ x,
                            const float* __restrict__ pc,
                            const float* __restrict__ pac,
                            const float* __restrict__ gamma,
                            const float* __restrict__ beta,
                            float* __restrict__ out)
{
    const int row = blockIdx.x;
    const size_t base = (size_t)row * DIMC;
    const int t = threadIdx.x;

    __shared__ float red[256];

    float y[3];
    float s = 0.0f;
#pragma unroll
    for (int i = 0; i < 3; i++) {
        int c = t + i * 256;
        y[i] = x[base + c] + pc[base + c] + pac[base + c];
        s += y[i];
    }
    red[t] = s;
    __syncthreads();
    for (int off = 128; off > 0; off >>= 1) {
        if (t < off) red[t] += red[t + off];
        __syncthreads();
    }
    float mu = red[0] * (1.0f / DIMC);
    __syncthreads();

    float vs = 0.0f;
#pragma unroll
    for (int i = 0; i < 3; i++) {
        float d = y[i] - mu;
        vs += d * d;
    }
    red[t] = vs;
    __syncthreads();
    for (int off = 128; off > 0; off >>= 1) {
        if (t < off) red[t] += red[t + off];
        __syncthreads();
    }
    float inv = rsqrtf(red[0] * (1.0f / DIMC) + 1e-5f);

#pragma unroll
    for (int i = 0; i < 3; i++) {
        int c = t + i * 256;
        out[base + c] = (y[i] - mu) * inv * gamma[c] + beta[c];
    }
}

// ============================================================================
// launch
// ============================================================================
#define GEMM_SMEM_128 ((GSTG * (A_STAGE + BK * (128 + 4))) * 4)
#define GEMM_SMEM_64  ((GSTG * (A_STAGE + BK * (64 + 4))) * 4)

extern "C" void kernel_launch(void* const* d_in, const int* in_sizes, int n_in,
                              void* d_out, int out_size)
{
    const float* x       = (const float*)d_in[0];
    const float* Wqkv_c  = (const float*)d_in[1];
    const float* bqkv_c  = (const float*)d_in[2];
    const float* Wp_c    = (const float*)d_in[3];
    const float* bp_c    = (const float*)d_in[4];
    const float* Wqkv_ac = (const float*)d_in[5];
    const float* bqkv_ac = (const float*)d_in[6];
    const float* Wp_ac   = (const float*)d_in[7];
    const float* bp_ac   = (const float*)d_in[8];
    const float* gamma   = (const float*)d_in[9];
    const float* beta    = (const float*)d_in[10];
    float* out = (float*)d_out;

    float *qkv_c, *qkv_ac, *attn_c, *attn_ac, *proj_c, *proj_ac;
    cudaGetSymbolAddress((void**)&qkv_c,  g_qkv_c);
    cudaGetSymbolAddress((void**)&qkv_ac, g_qkv_ac);
    cudaGetSymbolAddress((void**)&attn_c,  g_attn_c);
    cudaGetSymbolAddress((void**)&attn_ac, g_attn_ac);
    cudaGetSymbolAddress((void**)&proj_c,  g_proj_c);
    cudaGetSymbolAddress((void**)&proj_ac, g_proj_ac);

    cudaFuncSetAttribute(gemm_tf32_pipe<128>, cudaFuncAttributeMaxDynamicSharedMemorySize,
                         GEMM_SMEM_128);
    cudaFuncSetAttribute(gemm_tf32_pipe<64>, cudaFuncAttributeMaxDynamicSharedMemorySize,
                         GEMM_SMEM_64);
    cudaFuncSetAttribute(attn_mma, cudaFuncAttributeMaxDynamicSharedMemorySize,
                         AT_SMEM);

    dim3 blk256(256);

    // ---- QKV GEMMs, both branches in one launch (BN=128) ----
    gemm_tf32_pipe<128><<<dim3(QKV_N / 128, NROWS / BM, 2), blk256, GEMM_SMEM_128>>>(
        x, x, Wqkv_c, Wqkv_ac, bqkv_c, bqkv_ac, qkv_c, qkv_ac,
        NROWS, QKV_N, KDIM);

    // ---- attention: both branches in one launch ----
    attn_mma<<<dim3(T_SEQ / AT_BM, NH, 2 * B_SZ), dim3(128), AT_SMEM>>>(
        qkv_c, qkv_ac, attn_c, attn_ac);

    // ---- proj GEMMs, both branches in one launch (BN=64, better tail) ----
    gemm_tf32_pipe<64><<<dim3(DIMC / 64, NROWS / BM, 2), blk256, GEMM_SMEM_64>>>(
        attn_c, attn_ac, Wp_c, Wp_ac, bp_c, bp_ac, proj_c, proj_ac,
        NROWS, DIMC, KDIM);

    // ---- fused residual + layernorm ----
    residual_ln<<<NROWS, blk256>>>(x, proj_c, proj_ac, gamma, beta, out);
}